// round 1
// baseline (speedup 1.0000x reference)
#include <cuda_runtime.h>

// WindowAttention: B=64, H=W=56, C=192, NH=6, HD=32, WS=7, L=49, 4096 windows.
// Fused: window-gather -> QKV GEMMs -> per-head softmax attention -> out proj
// -> un-window scatter. One CTA per window, 256 threads, fp32 with packed
// fma.rn.f32x2 for 2x fp32 throughput in the GEMMs.

#define NH 6
#define HD 32
#define DIMC 192
#define LTOK 49
#define SCALE 0.17677669529663687f  // 1/sqrt(32)

typedef unsigned long long u64;

__device__ __forceinline__ u64 pk2(float x) {
    u64 r;
    asm("mov.b64 %0, {%1, %1};" : "=l"(r) : "f"(x));
    return r;
}
__device__ __forceinline__ u64 f2fma(u64 a, u64 b, u64 c) {
    u64 d;
    asm("fma.rn.f32x2 %0, %1, %2, %3;" : "=l"(d) : "l"(a), "l"(b), "l"(c));
    return d;
}

// Shared memory layout. xT doubles as aoT (attention output, channel-major)
// after the QKV GEMMs are done.
struct SM {
    float xT[192 * 64];    // [c][l] token-transposed window, XOR-swizzled; 49152 B
    float qs[49 * 200];    // [l][c] q, padded stride 200; 39200 B
    float ks[49 * 200];
    float vs[49 * 200];
    float prow[8 * 64];    // per-warp softmax row; 2048 B
};                          // total 168800 B

// 64-row(padded) x 192 x 192 GEMM fragment: thread computes rows r0..r0+3,
// cols c0..c0+11 (as 6 column-pairs), acc = bias + xT^T @ W.
// xT is [192][64] with column swizzle l ^ ((kk&15)<<2).
__device__ __forceinline__ void gemm192(const float* __restrict__ W,
                                        const float* __restrict__ bias,
                                        const float* xT, int r0, int c0,
                                        u64 acc[4][6]) {
#pragma unroll
    for (int j = 0; j < 6; j++) {
        u64 bb = *reinterpret_cast<const u64*>(bias + c0 + 2 * j);
#pragma unroll
        for (int i = 0; i < 4; i++) acc[i][j] = bb;
    }
#pragma unroll 4
    for (int kk = 0; kk < 192; kk++) {
        int sw = (kk & 15) << 2;
        float4 xv = *reinterpret_cast<const float4*>(xT + kk * 64 + (r0 ^ sw));
        u64 a0 = pk2(xv.x), a1 = pk2(xv.y), a2 = pk2(xv.z), a3 = pk2(xv.w);
        const ulonglong2* wr =
            reinterpret_cast<const ulonglong2*>(W + (size_t)kk * 192 + c0);
        ulonglong2 wA = wr[0], wB = wr[1], wC = wr[2];
        u64 wv[6] = {wA.x, wA.y, wB.x, wB.y, wC.x, wC.y};
#pragma unroll
        for (int j = 0; j < 6; j++) {
            u64 w = wv[j];
            acc[0][j] = f2fma(a0, w, acc[0][j]);
            acc[1][j] = f2fma(a1, w, acc[1][j]);
            acc[2][j] = f2fma(a2, w, acc[2][j]);
            acc[3][j] = f2fma(a3, w, acc[3][j]);
        }
    }
}

extern "C" __global__ void __launch_bounds__(256, 1)
win_attn_kernel(const float* __restrict__ x,
                const float* __restrict__ Wq, const float* __restrict__ bq,
                const float* __restrict__ Wk, const float* __restrict__ bk,
                const float* __restrict__ Wv, const float* __restrict__ bv,
                const float* __restrict__ Wo, const float* __restrict__ bo,
                float* __restrict__ out) {
    extern __shared__ char smem_raw[];
    SM* s = reinterpret_cast<SM*>(smem_raw);

    const int tid = threadIdx.x;
    const int warp = tid >> 5;
    const int lane = tid & 31;
    const int tx = tid & 15;
    const int ty = tid >> 4;
    const int r0 = ty * 4;      // token rows (padded to 64)
    const int c0 = tx * 12;     // output channel cols

    const int wid = blockIdx.x;          // window id
    const int b = wid >> 6;
    const int wh = (wid >> 3) & 7;
    const int ww = wid & 7;
    const size_t img_base = (size_t)b * 56 * 56 * 192;

    // ---- Phase 1: gather window into xT[c][l], swizzled ----
    for (int idx = tid; idx < LTOK * DIMC; idx += 256) {
        int l = idx / DIMC;
        int c = idx - l * DIMC;
        int i = l / 7, j = l - i * 7;
        int gy = wh * 7 + i, gx = ww * 7 + j;
        float v = x[img_base + ((size_t)(gy * 56 + gx)) * 192 + c];
        s->xT[c * 64 + (l ^ ((c & 15) << 2))] = v;
    }
    __syncthreads();

    // ---- Phase 2: QKV GEMMs ----
    u64 acc[4][6];
    if (r0 < LTOK) {
        gemm192(Wq, bq, s->xT, r0, c0, acc);
#pragma unroll
        for (int i = 0; i < 4; i++) {
            int r = r0 + i;
            if (r < LTOK) {
                u64* p = reinterpret_cast<u64*>(&s->qs[r * 200 + c0]);
#pragma unroll
                for (int j = 0; j < 6; j++) p[j] = acc[i][j];
            }
        }
        gemm192(Wk, bk, s->xT, r0, c0, acc);
#pragma unroll
        for (int i = 0; i < 4; i++) {
            int r = r0 + i;
            if (r < LTOK) {
                u64* p = reinterpret_cast<u64*>(&s->ks[r * 200 + c0]);
#pragma unroll
                for (int j = 0; j < 6; j++) p[j] = acc[i][j];
            }
        }
        gemm192(Wv, bv, s->xT, r0, c0, acc);
#pragma unroll
        for (int i = 0; i < 4; i++) {
            int r = r0 + i;
            if (r < LTOK) {
                u64* p = reinterpret_cast<u64*>(&s->vs[r * 200 + c0]);
#pragma unroll
                for (int j = 0; j < 6; j++) p[j] = acc[i][j];
            }
        }
    }
    __syncthreads();

    // ---- Phase 3: attention. 24 tasks = (head, l-phase mod 4), 3 per warp ----
    for (int t = warp; t < 24; t += 8) {
        const int h = t >> 2;
        const int par = t & 3;
        const int co = h * 32;

        // preload K rows (m = lane, m = lane+32) into registers
        float kr1[32], kr2[32];
        const int m2 = lane + 32;
        const int m2c = (m2 < LTOK) ? m2 : (LTOK - 1);
        const bool v2 = (m2 < LTOK);
#pragma unroll
        for (int d4 = 0; d4 < 8; d4++) {
            float4 ka = *reinterpret_cast<const float4*>(
                &s->ks[lane * 200 + co + d4 * 4]);
            kr1[d4 * 4 + 0] = ka.x; kr1[d4 * 4 + 1] = ka.y;
            kr1[d4 * 4 + 2] = ka.z; kr1[d4 * 4 + 3] = ka.w;
            float4 kb = *reinterpret_cast<const float4*>(
                &s->ks[m2c * 200 + co + d4 * 4]);
            kr2[d4 * 4 + 0] = kb.x; kr2[d4 * 4 + 1] = kb.y;
            kr2[d4 * 4 + 2] = kb.z; kr2[d4 * 4 + 3] = kb.w;
        }

        for (int li = par; li < LTOK; li += 4) {
            float s0a = 0.f, s0b = 0.f, s1a = 0.f, s1b = 0.f;
#pragma unroll
            for (int dd = 0; dd < 32; dd += 2) {
                float2 qv = *reinterpret_cast<const float2*>(
                    &s->qs[li * 200 + co + dd]);
                s0a = fmaf(qv.x, kr1[dd], s0a);
                s1a = fmaf(qv.x, kr2[dd], s1a);
                s0b = fmaf(qv.y, kr1[dd + 1], s0b);
                s1b = fmaf(qv.y, kr2[dd + 1], s1b);
            }
            float sc0 = (s0a + s0b) * SCALE;
            float sc1 = v2 ? (s1a + s1b) * SCALE : -1e30f;

            float mx = fmaxf(sc0, sc1);
#pragma unroll
            for (int o = 16; o > 0; o >>= 1)
                mx = fmaxf(mx, __shfl_xor_sync(0xffffffffu, mx, o));
            float e0 = __expf(sc0 - mx);
            float e1 = v2 ? __expf(sc1 - mx) : 0.f;
            float sum = e0 + e1;
#pragma unroll
            for (int o = 16; o > 0; o >>= 1)
                sum += __shfl_xor_sync(0xffffffffu, sum, o);
            float inv = __fdividef(1.f, sum);

            s->prow[warp * 64 + lane] = e0 * inv;
            s->prow[warp * 64 + lane + 32] = e1 * inv;
            __syncwarp();

            // AV: lane owns head-dim d = lane
            float oa = 0.f, ob = 0.f;
            const float* pr = &s->prow[warp * 64];
#pragma unroll
            for (int m = 0; m < 48; m += 2) {
                oa = fmaf(pr[m], s->vs[m * 200 + co + lane], oa);
                ob = fmaf(pr[m + 1], s->vs[(m + 1) * 200 + co + lane], ob);
            }
            oa = fmaf(pr[48], s->vs[48 * 200 + co + lane], oa);

            int n = co + lane;  // channel index
            s->xT[n * 64 + (li ^ ((n & 15) << 2))] = oa + ob;  // aoT reuse
            __syncwarp();
        }
    }
    __syncthreads();

    // ---- Phase 4: output projection + un-window scatter ----
    if (r0 < LTOK) {
        gemm192(Wo, bo, s->xT, r0, c0, acc);
#pragma unroll
        for (int i = 0; i < 4; i++) {
            int r = r0 + i;
            if (r < LTOK) {
                int ii = r / 7, jj = r - ii * 7;
                int gy = wh * 7 + ii, gx = ww * 7 + jj;
                u64* p = reinterpret_cast<u64*>(
                    out + img_base + ((size_t)(gy * 56 + gx)) * 192 + c0);
#pragma unroll
                for (int j = 0; j < 6; j++) p[j] = acc[i][j];
            }
        }
    }
}

extern "C" void kernel_launch(void* const* d_in, const int* in_sizes, int n_in,
                              void* d_out, int out_size) {
    const float* x  = (const float*)d_in[0];
    const float* Wq = (const float*)d_in[1];
    const float* bq = (const float*)d_in[2];
    const float* Wk = (const float*)d_in[3];
    const float* bk = (const float*)d_in[4];
    const float* Wv = (const float*)d_in[5];
    const float* bv = (const float*)d_in[6];
    const float* Wo = (const float*)d_in[7];
    const float* bo = (const float*)d_in[8];
    float* out = (float*)d_out;

    cudaFuncSetAttribute(win_attn_kernel,
                         cudaFuncAttributeMaxDynamicSharedMemorySize,
                         (int)sizeof(SM));
    win_attn_kernel<<<4096, 256, sizeof(SM)>>>(x, Wq, bq, Wk, bk, Wv, bv,
                                               Wo, bo, out);
}

// round 3
// speedup vs baseline: 1.6925x; 1.6925x over previous
#include <cuda_runtime.h>
#include <cuda_bf16.h>
#include <cstdint>

// WindowAttention B=64 56x56 C=192 NH=6 HD=32 WS=7 -> 4096 windows x 49 tokens.
// K0 prep:   W -> W^T [N][K] bf16 hi/lo split; bias concat
// K1 gemm0:  qkv = x @ [Wq|Wk|Wv] + b   (mma.sync bf16, 3-pass hi/lo split)
// K2 attn:   per-window softmax attention (register-P, f32x2 QK)
// K3 gemm1:  out = attn @ Wo + bo       (same gemm kernel, mode=1)

#define TOKENS 200704
#define DIMC 192
#define NQKV 576
#define LTOK 49
#define SCALE 0.17677669529663687f
#define MT 128
#define NT 96
#define AS 200   // A smem stride (bf16 elems)
#define BS 200   // B smem stride (bf16 elems)

typedef unsigned long long u64;

// ---------------- device scratch ----------------------------------------
__device__ __align__(16) float g_qkv[(size_t)TOKENS * NQKV];
__device__ __align__(16) float g_attn[(size_t)TOKENS * DIMC];
__device__ __align__(16) uint16_t g_WThi[NQKV * DIMC];
__device__ __align__(16) uint16_t g_WTlo[NQKV * DIMC];
__device__ __align__(16) uint16_t g_WoThi[DIMC * DIMC];
__device__ __align__(16) uint16_t g_WoTlo[DIMC * DIMC];
__device__ __align__(16) float g_bqkv[NQKV];

// ---------------- helpers ------------------------------------------------
__device__ __forceinline__ u64 pk2(float x) {
    u64 r;
    asm("mov.b64 %0, {%1, %1};" : "=l"(r) : "f"(x));
    return r;
}
__device__ __forceinline__ u64 pkab(float a, float b) {
    u64 r;
    asm("mov.b64 %0, {%1, %2};" : "=l"(r) : "f"(a), "f"(b));
    return r;
}
__device__ __forceinline__ void unpk(u64 v, float& a, float& b) {
    asm("mov.b64 {%0, %1}, %2;" : "=f"(a), "=f"(b) : "l"(v));
}
__device__ __forceinline__ u64 f2fma(u64 a, u64 b, u64 c) {
    u64 d;
    asm("fma.rn.f32x2 %0, %1, %2, %3;" : "=l"(d) : "l"(a), "l"(b), "l"(c));
    return d;
}
__device__ __forceinline__ void mma_bf16(float d[4], const uint32_t a[4],
                                         const uint32_t b[2]) {
    asm volatile(
        "mma.sync.aligned.m16n8k16.row.col.f32.bf16.bf16.f32 "
        "{%0,%1,%2,%3}, {%4,%5,%6,%7}, {%8,%9}, {%0,%1,%2,%3};"
        : "+f"(d[0]), "+f"(d[1]), "+f"(d[2]), "+f"(d[3])
        : "r"(a[0]), "r"(a[1]), "r"(a[2]), "r"(a[3]), "r"(b[0]), "r"(b[1]));
}
__device__ __forceinline__ uint32_t bf2pack(float x, float y) {
    __nv_bfloat16 hx = __float2bfloat16(x), hy = __float2bfloat16(y);
    return ((uint32_t)__bfloat16_as_ushort(hy) << 16) | __bfloat16_as_ushort(hx);
}

// ---------------- K0: weight transpose + bf16 split ----------------------
__global__ void prep_kernel(const float* __restrict__ Wq, const float* __restrict__ Wk,
                            const float* __restrict__ Wv, const float* __restrict__ Wo,
                            const float* __restrict__ bq, const float* __restrict__ bk,
                            const float* __restrict__ bv) {
    int idx = blockIdx.x * 256 + threadIdx.x;
    if (idx < NQKV * DIMC) {
        int n = idx / DIMC, k = idx - n * DIMC;
        const float* W = (n < 192) ? Wq : (n < 384) ? Wk : Wv;
        float v = W[k * DIMC + (n % 192)];
        __nv_bfloat16 h = __float2bfloat16(v);
        g_WThi[idx] = __bfloat16_as_ushort(h);
        g_WTlo[idx] = __bfloat16_as_ushort(__float2bfloat16(v - __bfloat162float(h)));
        if (idx < NQKV) {
            g_bqkv[idx] = (idx < 192) ? bq[idx]
                        : (idx < 384) ? bk[idx - 192] : bv[idx - 384];
        }
    } else if (idx < NQKV * DIMC + DIMC * DIMC) {
        int j = idx - NQKV * DIMC;
        int n = j / DIMC, k = j - n * DIMC;
        float v = Wo[k * DIMC + n];
        __nv_bfloat16 h = __float2bfloat16(v);
        g_WoThi[j] = __bfloat16_as_ushort(h);
        g_WoTlo[j] = __bfloat16_as_ushort(__float2bfloat16(v - __bfloat162float(h)));
    }
}

// ---------------- K1/K3: HMMA GEMM (+bias) -------------------------------
// smem: Ahi[128*200], Alo, Bhi[96*200], Blo  (bf16) = 179200 B
#define SM_AHI 0
#define SM_ALO (MT * AS)
#define SM_BHI (2 * MT * AS)
#define SM_BLO (2 * MT * AS + NT * BS)
#define GEMM_SMEM ((2 * MT * AS + 2 * NT * BS) * 2)

extern "C" __global__ void __launch_bounds__(256, 1)
gemm_kernel(const float* __restrict__ x, const float* __restrict__ bo,
            float* __restrict__ outx, int mode) {
    extern __shared__ uint16_t sm[];
    const int tid = threadIdx.x, wid = tid >> 5, lane = tid & 31;
    const int ntile = blockIdx.x, mtile = blockIdx.y;
    const int Ntot = mode ? DIMC : NQKV;
    const float* A = mode ? g_attn : x;
    const uint16_t* Bhi = mode ? g_WoThi : g_WThi;
    const uint16_t* Blo = mode ? g_WoTlo : g_WTlo;
    const float* bias = mode ? bo : g_bqkv;
    float* outp = mode ? outx : g_qkv;

    // ---- load A tile: fp32 -> bf16 hi/lo ----
    const float* Arow = A + (size_t)mtile * MT * DIMC;
    for (int idx = tid; idx < MT * 48; idx += 256) {
        int r = idx / 48, kq = idx - r * 48, k = kq * 4;
        float4 v = *(const float4*)(Arow + r * DIMC + k);
        float hx = __bfloat162float(__float2bfloat16(v.x));
        float hy = __bfloat162float(__float2bfloat16(v.y));
        float hz = __bfloat162float(__float2bfloat16(v.z));
        float hw = __bfloat162float(__float2bfloat16(v.w));
        uint32_t* ph = (uint32_t*)(sm + SM_AHI + r * AS + k);
        uint32_t* pl = (uint32_t*)(sm + SM_ALO + r * AS + k);
        ph[0] = bf2pack(v.x, v.y);
        ph[1] = bf2pack(v.z, v.w);
        pl[0] = bf2pack(v.x - hx, v.y - hy);
        pl[1] = bf2pack(v.z - hz, v.w - hw);
    }
    // ---- load B tile (already bf16) ----
    for (int idx = tid; idx < NT * 24; idx += 256) {
        int r = idx / 24, ko = idx - r * 24, k = ko * 8;
        int ng = ntile * NT + r;
        *(uint4*)(sm + SM_BHI + r * BS + k) = *(const uint4*)(Bhi + ng * DIMC + k);
        *(uint4*)(sm + SM_BLO + r * BS + k) = *(const uint4*)(Blo + ng * DIMC + k);
    }
    __syncthreads();

    const int g = lane >> 2, tg = lane & 3;
    const int wm = (wid >> 1) * 32;       // warp M offset (4 groups)
    const int wn = (wid & 1) * 48;        // warp N offset (2 groups)

    float acc[2][6][4];
#pragma unroll
    for (int mi = 0; mi < 2; mi++)
#pragma unroll
        for (int ni = 0; ni < 6; ni++)
#pragma unroll
            for (int q = 0; q < 4; q++) acc[mi][ni][q] = 0.f;

    const int aoff[3] = {SM_AHI, SM_AHI, SM_ALO};
    const int boff[3] = {SM_BHI, SM_BLO, SM_BHI};

#pragma unroll
    for (int p = 0; p < 3; p++) {
        const uint16_t* Ap = sm + aoff[p];
        const uint16_t* Bp = sm + boff[p];
#pragma unroll
        for (int ks = 0; ks < 12; ks++) {
            const int kb = ks * 16;
            uint32_t a[2][4];
#pragma unroll
            for (int mi = 0; mi < 2; mi++) {
                const uint16_t* ap = Ap + (wm + mi * 16 + g) * AS + kb + tg * 2;
                a[mi][0] = *(const uint32_t*)(ap);
                a[mi][1] = *(const uint32_t*)(ap + 8 * AS);
                a[mi][2] = *(const uint32_t*)(ap + 8);
                a[mi][3] = *(const uint32_t*)(ap + 8 * AS + 8);
            }
#pragma unroll
            for (int ni = 0; ni < 6; ni++) {
                const uint16_t* bp = Bp + (wn + ni * 8 + g) * BS + kb + tg * 2;
                uint32_t b[2];
                b[0] = *(const uint32_t*)(bp);
                b[1] = *(const uint32_t*)(bp + 8);
                mma_bf16(acc[0][ni], a[0], b);
                mma_bf16(acc[1][ni], a[1], b);
            }
        }
    }

    // ---- epilogue: add bias, store ----
#pragma unroll
    for (int mi = 0; mi < 2; mi++) {
        size_t r0 = (size_t)mtile * MT + wm + mi * 16 + g;
#pragma unroll
        for (int ni = 0; ni < 6; ni++) {
            int cg = ntile * NT + wn + ni * 8 + tg * 2;
            float2 bb = *(const float2*)(bias + cg);
            float2 o0 = {acc[mi][ni][0] + bb.x, acc[mi][ni][1] + bb.y};
            float2 o1 = {acc[mi][ni][2] + bb.x, acc[mi][ni][3] + bb.y};
            *(float2*)(outp + r0 * Ntot + cg) = o0;
            *(float2*)(outp + (r0 + 8) * Ntot + cg) = o1;
        }
    }
}

// ---------------- K2: per-window attention -------------------------------
// smem: qs[49*192], ks[49*196], vs[49*192] floats = 113680 B  (2 CTA/SM)
#define QS_ST 192
#define KS_ST 196
#define VS_ST 192
#define ATTN_SMEM ((LTOK * (QS_ST + KS_ST + VS_ST)) * 4)

extern "C" __global__ void __launch_bounds__(256, 2) attn_kernel() {
    extern __shared__ float sf[];
    float* qs = sf;
    float* ks = qs + LTOK * QS_ST;
    float* vs = ks + LTOK * KS_ST;

    const int tid = threadIdx.x;
    const int warp = tid >> 5, lane = tid & 31;
    const int widx = blockIdx.x;
    const int b = widx >> 6, wh = (widx >> 3) & 7, ww = widx & 7;
    const size_t wrow0 = (size_t)b * 3136 + (size_t)wh * 7 * 56 + ww * 7;

    for (int idx = tid; idx < LTOK * 48; idx += 256) {
        int l = idx / 48, kq = idx - l * 48;
        int i = l / 7, j = l - i * 7;
        const float* src = g_qkv + (wrow0 + i * 56 + j) * NQKV + kq * 4;
        *(float4*)&qs[l * QS_ST + kq * 4] = *(const float4*)(src);
        *(float4*)&ks[l * KS_ST + kq * 4] = *(const float4*)(src + 192);
        *(float4*)&vs[l * VS_ST + kq * 4] = *(const float4*)(src + 384);
    }
    __syncthreads();

    const int m2 = lane + 32;
    const bool v2 = (m2 < LTOK);
    const int m2c = v2 ? m2 : (LTOK - 1);
    const int qstart[4] = {0, 13, 26, 39};
    const int qend[4] = {13, 26, 39, 49};

    for (int t = warp; t < 24; t += 8) {
        const int h = t >> 2, par = t & 3, co = h * 32;

        // preload K rows (lane, lane+32) interleaved as f32x2 pairs
        u64 kp[32];
#pragma unroll
        for (int d4 = 0; d4 < 8; d4++) {
            float4 ka = *(const float4*)&ks[lane * KS_ST + co + d4 * 4];
            float4 kb = *(const float4*)&ks[m2c * KS_ST + co + d4 * 4];
            kp[d4 * 4 + 0] = pkab(ka.x, kb.x);
            kp[d4 * 4 + 1] = pkab(ka.y, kb.y);
            kp[d4 * 4 + 2] = pkab(ka.z, kb.z);
            kp[d4 * 4 + 3] = pkab(ka.w, kb.w);
        }

        const int ls = qstart[par], le = qend[par];
        for (int li0 = ls; li0 < le; li0 += 4) {
            float p0[4], p1[4];
#pragma unroll
            for (int u = 0; u < 4; u++) {
                int li = li0 + u;
                int lic = (li < le) ? li : ls;
                u64 s01 = pkab(0.f, 0.f);
#pragma unroll
                for (int dd = 0; dd < 32; dd += 2) {
                    float2 qv = *(const float2*)&qs[lic * QS_ST + co + dd];
                    s01 = f2fma(pk2(qv.x), kp[dd], s01);
                    s01 = f2fma(pk2(qv.y), kp[dd + 1], s01);
                }
                float s0, s1;
                unpk(s01, s0, s1);
                float e0 = __expf(s0 * SCALE);
                float e1 = v2 ? __expf(s1 * SCALE) : 0.f;
                float sum = e0 + e1;
#pragma unroll
                for (int o = 16; o > 0; o >>= 1)
                    sum += __shfl_xor_sync(0xffffffffu, sum, o);
                float inv = __fdividef(1.f, sum);
                p0[u] = e0 * inv;
                p1[u] = e1 * inv;
            }

            float accv[4] = {0.f, 0.f, 0.f, 0.f};
#pragma unroll 7
            for (int m = 0; m < 32; m++) {
                float v = vs[m * VS_ST + co + lane];
#pragma unroll
                for (int u = 0; u < 4; u++)
                    accv[u] = fmaf(__shfl_sync(0xffffffffu, p0[u], m), v, accv[u]);
            }
#pragma unroll 7
            for (int m = 32; m < 49; m++) {
                float v = vs[m * VS_ST + co + lane];
#pragma unroll
                for (int u = 0; u < 4; u++)
                    accv[u] = fmaf(__shfl_sync(0xffffffffu, p1[u], m - 32), v, accv[u]);
            }
#pragma unroll
            for (int u = 0; u < 4; u++) {
                int li = li0 + u;
                if (li < le) {
                    int i2 = li / 7, j2 = li - i2 * 7;
                    g_attn[(wrow0 + i2 * 56 + j2) * DIMC + co + lane] = accv[u];
                }
            }
        }
    }
}

// ---------------- launch --------------------------------------------------
extern "C" void kernel_launch(void* const* d_in, const int* in_sizes, int n_in,
                              void* d_out, int out_size) {
    const float* x  = (const float*)d_in[0];
    const float* Wq = (const float*)d_in[1];
    const float* bq = (const float*)d_in[2];
    const float* Wk = (const float*)d_in[3];
    const float* bk = (const float*)d_in[4];
    const float* Wv = (const float*)d_in[5];
    const float* bv = (const float*)d_in[6];
    const float* Wo = (const float*)d_in[7];
    const float* bo = (const float*)d_in[8];
    float* out = (float*)d_out;

    cudaFuncSetAttribute(gemm_kernel, cudaFuncAttributeMaxDynamicSharedMemorySize,
                         GEMM_SMEM);
    cudaFuncSetAttribute(attn_kernel, cudaFuncAttributeMaxDynamicSharedMemorySize,
                         ATTN_SMEM);

    prep_kernel<<<(NQKV * DIMC + DIMC * DIMC + 255) / 256, 256>>>(Wq, Wk, Wv, Wo,
                                                                  bq, bk, bv);
    gemm_kernel<<<dim3(6, TOKENS / MT), 256, GEMM_SMEM>>>(x, bo, out, 0);
    attn_kernel<<<4096, 256, ATTN_SMEM>>>();
    gemm_kernel<<<dim3(2, TOKENS / MT), 256, GEMM_SMEM>>>(x, bo, out, 1);
}

// round 4
// speedup vs baseline: 2.4252x; 1.4329x over previous
#include <cuda_runtime.h>
#include <cuda_bf16.h>
#include <cstdint>

// WindowAttention B=64 56x56 C=192 NH=6 HD=32 WS=7 -> 4096 windows x 49 tokens.
// K0 prep:    W -> W^T bf16 hi/lo, bias concat
// K0b xsplit: x fp32 -> bf16 hi/lo
// K1 gemm0:   qkv = x @ [Wq|Wk|Wv] + b  (mma.sync bf16 3-pass, cp.async pipe)
// K2 attn:    per-window softmax attention; writes bf16 hi/lo
// K3 gemm1:   out = attn @ Wo + bo

#define TOKENS 200704
#define DIMC 192
#define NQKV 576
#define LTOK 49
#define SCALE 0.17677669529663687f
#define MT 64
#define NTILE 192
#define KC 48
#define AST 56   // A smem row stride (bf16 elems)
#define BST 48   // B smem row stride

typedef unsigned long long u64;

// ---------------- device scratch ----------------------------------------
__device__ __align__(16) float g_qkv[(size_t)TOKENS * NQKV];
__device__ __align__(16) uint16_t g_xHi[(size_t)TOKENS * DIMC];
__device__ __align__(16) uint16_t g_xLo[(size_t)TOKENS * DIMC];
__device__ __align__(16) uint16_t g_attnHi[(size_t)TOKENS * DIMC];
__device__ __align__(16) uint16_t g_attnLo[(size_t)TOKENS * DIMC];
__device__ __align__(16) uint16_t g_WThi[NQKV * DIMC];
__device__ __align__(16) uint16_t g_WTlo[NQKV * DIMC];
__device__ __align__(16) uint16_t g_WoThi[DIMC * DIMC];
__device__ __align__(16) uint16_t g_WoTlo[DIMC * DIMC];
__device__ __align__(16) float g_bqkv[NQKV];

// ---------------- helpers ------------------------------------------------
__device__ __forceinline__ uint32_t smem_u32(const void* p) {
    uint32_t a;
    asm("{ .reg .u64 t; cvta.to.shared.u64 t, %1; cvt.u32.u64 %0, t; }"
        : "=r"(a) : "l"(p));
    return a;
}
__device__ __forceinline__ u64 pk2(float x) {
    u64 r; asm("mov.b64 %0, {%1, %1};" : "=l"(r) : "f"(x)); return r;
}
__device__ __forceinline__ u64 pkab(float a, float b) {
    u64 r; asm("mov.b64 %0, {%1, %2};" : "=l"(r) : "f"(a), "f"(b)); return r;
}
__device__ __forceinline__ void unpk(u64 v, float& a, float& b) {
    asm("mov.b64 {%0, %1}, %2;" : "=f"(a), "=f"(b) : "l"(v));
}
__device__ __forceinline__ u64 f2fma(u64 a, u64 b, u64 c) {
    u64 d; asm("fma.rn.f32x2 %0, %1, %2, %3;" : "=l"(d) : "l"(a), "l"(b), "l"(c));
    return d;
}
__device__ __forceinline__ void mma_bf16(float d[4], const uint32_t a[4],
                                         const uint32_t b[2]) {
    asm volatile(
        "mma.sync.aligned.m16n8k16.row.col.f32.bf16.bf16.f32 "
        "{%0,%1,%2,%3}, {%4,%5,%6,%7}, {%8,%9}, {%0,%1,%2,%3};"
        : "+f"(d[0]), "+f"(d[1]), "+f"(d[2]), "+f"(d[3])
        : "r"(a[0]), "r"(a[1]), "r"(a[2]), "r"(a[3]), "r"(b[0]), "r"(b[1]));
}
__device__ __forceinline__ uint32_t bf2pack(float x, float y) {
    __nv_bfloat16 hx = __float2bfloat16(x), hy = __float2bfloat16(y);
    return ((uint32_t)__bfloat16_as_ushort(hy) << 16) | __bfloat16_as_ushort(hx);
}
__device__ __forceinline__ void cpa16(uint32_t dst, const void* src) {
    asm volatile("cp.async.cg.shared.global [%0], [%1], 16;"
                 :: "r"(dst), "l"(src));
}
#define CP_COMMIT() asm volatile("cp.async.commit_group;" ::: "memory")
#define CP_WAIT1() asm volatile("cp.async.wait_group 1;" ::: "memory")
#define CP_WAIT0() asm volatile("cp.async.wait_group 0;" ::: "memory")

// ---------------- K0: weight prep ----------------------------------------
__global__ void prep_kernel(const float* __restrict__ Wq, const float* __restrict__ Wk,
                            const float* __restrict__ Wv, const float* __restrict__ Wo,
                            const float* __restrict__ bq, const float* __restrict__ bk,
                            const float* __restrict__ bv) {
    int idx = blockIdx.x * 256 + threadIdx.x;
    if (idx < NQKV * DIMC) {
        int n = idx / DIMC, k = idx - n * DIMC;
        const float* W = (n < 192) ? Wq : (n < 384) ? Wk : Wv;
        float v = W[k * DIMC + (n % 192)];
        __nv_bfloat16 h = __float2bfloat16(v);
        g_WThi[idx] = __bfloat16_as_ushort(h);
        g_WTlo[idx] = __bfloat16_as_ushort(__float2bfloat16(v - __bfloat162float(h)));
        if (idx < NQKV)
            g_bqkv[idx] = (idx < 192) ? bq[idx]
                        : (idx < 384) ? bk[idx - 192] : bv[idx - 384];
    } else if (idx < NQKV * DIMC + DIMC * DIMC) {
        int j = idx - NQKV * DIMC;
        int n = j / DIMC, k = j - n * DIMC;
        float v = Wo[k * DIMC + n];
        __nv_bfloat16 h = __float2bfloat16(v);
        g_WoThi[j] = __bfloat16_as_ushort(h);
        g_WoTlo[j] = __bfloat16_as_ushort(__float2bfloat16(v - __bfloat162float(h)));
    }
}

// ---------------- K0b: x -> bf16 hi/lo -----------------------------------
__global__ void xsplit_kernel(const float* __restrict__ x) {
    size_t i4 = ((size_t)blockIdx.x * 256 + threadIdx.x) * 4;
    float4 v = *(const float4*)(x + i4);
    float hx = __bfloat162float(__float2bfloat16(v.x));
    float hy = __bfloat162float(__float2bfloat16(v.y));
    float hz = __bfloat162float(__float2bfloat16(v.z));
    float hw = __bfloat162float(__float2bfloat16(v.w));
    *(uint2*)(g_xHi + i4) = make_uint2(bf2pack(v.x, v.y), bf2pack(v.z, v.w));
    *(uint2*)(g_xLo + i4) = make_uint2(bf2pack(v.x - hx, v.y - hy),
                                       bf2pack(v.z - hz, v.w - hw));
}

// ---------------- K1/K3: pipelined HMMA GEMM ------------------------------
// smem (uint16 units): Ahi 2x3584, Alo 2x3584, Bhi 2x9216, Blo 2x9216
#define SA_HI 0
#define SA_LO 7168
#define SB_HI 14336
#define SB_LO 32768
#define GEMM_SMEM (51200 * 2)

__device__ __forceinline__ void load_chunk(
    uint32_t sbase, int buf, int c, int tid, size_t arow0, int ncol0,
    const uint16_t* __restrict__ Ahg, const uint16_t* __restrict__ Alg,
    const uint16_t* __restrict__ Bhg, const uint16_t* __restrict__ Blg) {
    // A: 64 rows x 48 elems, hi+lo
    for (int idx = tid; idx < MT * 6; idx += 256) {
        int r = idx / 6, kk = idx - r * 6;
        uint32_t off = (uint32_t)(r * AST + kk * 8) * 2;
        size_t gs = (arow0 + r) * DIMC + c * KC + kk * 8;
        cpa16(sbase + (SA_HI + buf * 3584) * 2 + off, Ahg + gs);
        cpa16(sbase + (SA_LO + buf * 3584) * 2 + off, Alg + gs);
    }
    // B: 192 rows x 48 elems, hi+lo
    for (int idx = tid; idx < NTILE * 6; idx += 256) {
        int r = idx / 6, kk = idx - r * 6;
        uint32_t off = (uint32_t)(r * BST + kk * 8) * 2;
        size_t gs = (size_t)(ncol0 + r) * DIMC + c * KC + kk * 8;
        cpa16(sbase + (SB_HI + buf * 9216) * 2 + off, Bhg + gs);
        cpa16(sbase + (SB_LO + buf * 9216) * 2 + off, Blg + gs);
    }
}

extern "C" __global__ void __launch_bounds__(256, 2)
gemm_kernel(const float* __restrict__ bo, float* __restrict__ outx, int mode) {
    extern __shared__ uint16_t sm[];
    uint32_t sbase = smem_u32(sm);
    const int tid = threadIdx.x, wid = tid >> 5, lane = tid & 31;
    const int g = lane >> 2, tg = lane & 3;
    const int wm = (wid >> 2) * 32;     // 2 warp rows
    const int wn = (wid & 3) * 48;      // 4 warp cols
    const int mtile = blockIdx.y;
    const int ncol0 = blockIdx.x * NTILE;
    const size_t arow0 = (size_t)mtile * MT;

    const uint16_t* Ahg = mode ? g_attnHi : g_xHi;
    const uint16_t* Alg = mode ? g_attnLo : g_xLo;
    const uint16_t* Bhg = mode ? g_WoThi : g_WThi;
    const uint16_t* Blg = mode ? g_WoTlo : g_WTlo;
    const float* bias = mode ? bo : g_bqkv;
    const int Ntot = mode ? DIMC : NQKV;
    float* outp = mode ? outx : g_qkv;

    float acc[2][6][4];
#pragma unroll
    for (int mi = 0; mi < 2; mi++)
#pragma unroll
        for (int ni = 0; ni < 6; ni++)
#pragma unroll
            for (int q = 0; q < 4; q++) acc[mi][ni][q] = 0.f;

    load_chunk(sbase, 0, 0, tid, arow0, ncol0, Ahg, Alg, Bhg, Blg);
    CP_COMMIT();
    load_chunk(sbase, 1, 1, tid, arow0, ncol0, Ahg, Alg, Bhg, Blg);
    CP_COMMIT();

#pragma unroll
    for (int c = 0; c < 4; c++) {
        if (c < 3) { CP_WAIT1(); } else { CP_WAIT0(); }
        __syncthreads();
        const int buf = c & 1;
        const uint16_t* Ah = sm + SA_HI + buf * 3584;
        const uint16_t* Al = sm + SA_LO + buf * 3584;
        const uint16_t* Bh = sm + SB_HI + buf * 9216;
        const uint16_t* Bl = sm + SB_LO + buf * 9216;
#pragma unroll
        for (int ks = 0; ks < 3; ks++) {
            const int kb = ks * 16;
            uint32_t ah[2][4], al[2][4];
#pragma unroll
            for (int mi = 0; mi < 2; mi++) {
                const uint16_t* ap = Ah + (wm + mi * 16 + g) * AST + kb + tg * 2;
                ah[mi][0] = *(const uint32_t*)(ap);
                ah[mi][1] = *(const uint32_t*)(ap + 8 * AST);
                ah[mi][2] = *(const uint32_t*)(ap + 8);
                ah[mi][3] = *(const uint32_t*)(ap + 8 * AST + 8);
                const uint16_t* alp = Al + (wm + mi * 16 + g) * AST + kb + tg * 2;
                al[mi][0] = *(const uint32_t*)(alp);
                al[mi][1] = *(const uint32_t*)(alp + 8 * AST);
                al[mi][2] = *(const uint32_t*)(alp + 8);
                al[mi][3] = *(const uint32_t*)(alp + 8 * AST + 8);
            }
#pragma unroll
            for (int ni = 0; ni < 6; ni++) {
                const uint16_t* bph = Bh + (wn + ni * 8 + g) * BST + kb + tg * 2;
                const uint16_t* bpl = Bl + (wn + ni * 8 + g) * BST + kb + tg * 2;
                uint32_t bh[2] = {*(const uint32_t*)bph, *(const uint32_t*)(bph + 8)};
                uint32_t bl[2] = {*(const uint32_t*)bpl, *(const uint32_t*)(bpl + 8)};
                mma_bf16(acc[0][ni], ah[0], bh);
                mma_bf16(acc[1][ni], ah[1], bh);
                mma_bf16(acc[0][ni], ah[0], bl);
                mma_bf16(acc[1][ni], ah[1], bl);
                mma_bf16(acc[0][ni], al[0], bh);
                mma_bf16(acc[1][ni], al[1], bh);
            }
        }
        if (c + 2 < 4) {
            __syncthreads();
            load_chunk(sbase, buf, c + 2, tid, arow0, ncol0, Ahg, Alg, Bhg, Blg);
            CP_COMMIT();
        }
    }

    // ---- epilogue ----
#pragma unroll
    for (int mi = 0; mi < 2; mi++) {
        size_t r0 = arow0 + wm + mi * 16 + g;
#pragma unroll
        for (int ni = 0; ni < 6; ni++) {
            int cg = ncol0 + wn + ni * 8 + tg * 2;
            float2 bb = *(const float2*)(bias + cg);
            float2 o0 = {acc[mi][ni][0] + bb.x, acc[mi][ni][1] + bb.y};
            float2 o1 = {acc[mi][ni][2] + bb.x, acc[mi][ni][3] + bb.y};
            *(float2*)(outp + r0 * Ntot + cg) = o0;
            *(float2*)(outp + (r0 + 8) * Ntot + cg) = o1;
        }
    }
}

// ---------------- K2: per-window attention --------------------------------
#define QS_ST 192
#define KS_ST 196
#define VS_ST 192
#define ATTN_SMEM ((LTOK * (QS_ST + KS_ST + VS_ST)) * 4)

extern "C" __global__ void __launch_bounds__(256, 2) attn_kernel() {
    extern __shared__ float sf[];
    float* qs = sf;
    float* ks = qs + LTOK * QS_ST;
    float* vs = ks + LTOK * KS_ST;

    const int tid = threadIdx.x;
    const int warp = tid >> 5, lane = tid & 31;
    const int widx = blockIdx.x;
    const int b = widx >> 6, wh = (widx >> 3) & 7, ww = widx & 7;
    const size_t wrow0 = (size_t)b * 3136 + (size_t)wh * 7 * 56 + ww * 7;

    for (int idx = tid; idx < LTOK * 48; idx += 256) {
        int l = idx / 48, kq = idx - l * 48;
        int i = l / 7, j = l - i * 7;
        const float* src = g_qkv + (wrow0 + i * 56 + j) * NQKV + kq * 4;
        *(float4*)&qs[l * QS_ST + kq * 4] = *(const float4*)(src);
        *(float4*)&ks[l * KS_ST + kq * 4] = *(const float4*)(src + 192);
        *(float4*)&vs[l * VS_ST + kq * 4] = *(const float4*)(src + 384);
    }
    __syncthreads();

    const int m2 = lane + 32;
    const bool v2 = (m2 < LTOK);
    const int m2c = v2 ? m2 : (LTOK - 1);
    const int qstart[4] = {0, 13, 26, 39};
    const int qend[4] = {13, 26, 39, 49};

    for (int t = warp; t < 24; t += 8) {
        const int h = t >> 2, par = t & 3, co = h * 32;

        u64 kp[32];
#pragma unroll
        for (int d4 = 0; d4 < 8; d4++) {
            float4 ka = *(const float4*)&ks[lane * KS_ST + co + d4 * 4];
            float4 kb = *(const float4*)&ks[m2c * KS_ST + co + d4 * 4];
            kp[d4 * 4 + 0] = pkab(ka.x, kb.x);
            kp[d4 * 4 + 1] = pkab(ka.y, kb.y);
            kp[d4 * 4 + 2] = pkab(ka.z, kb.z);
            kp[d4 * 4 + 3] = pkab(ka.w, kb.w);
        }

        const int ls = qstart[par], le = qend[par];
        for (int li0 = ls; li0 < le; li0 += 4) {
            float p0[4], p1[4];
#pragma unroll
            for (int u = 0; u < 4; u++) {
                int li = li0 + u;
                int lic = (li < le) ? li : ls;
                u64 s01 = pkab(0.f, 0.f);
#pragma unroll
                for (int dd = 0; dd < 32; dd += 2) {
                    float2 qv = *(const float2*)&qs[lic * QS_ST + co + dd];
                    s01 = f2fma(pk2(qv.x), kp[dd], s01);
                    s01 = f2fma(pk2(qv.y), kp[dd + 1], s01);
                }
                float s0, s1;
                unpk(s01, s0, s1);
                float e0 = __expf(s0 * SCALE);
                float e1 = v2 ? __expf(s1 * SCALE) : 0.f;
                float sum = e0 + e1;
#pragma unroll
                for (int o = 16; o > 0; o >>= 1)
                    sum += __shfl_xor_sync(0xffffffffu, sum, o);
                float inv = __fdividef(1.f, sum);
                p0[u] = e0 * inv;
                p1[u] = e1 * inv;
            }

            float accv[4] = {0.f, 0.f, 0.f, 0.f};
#pragma unroll 7
            for (int m = 0; m < 32; m++) {
                float v = vs[m * VS_ST + co + lane];
#pragma unroll
                for (int u = 0; u < 4; u++)
                    accv[u] = fmaf(__shfl_sync(0xffffffffu, p0[u], m), v, accv[u]);
            }
#pragma unroll 7
            for (int m = 32; m < 49; m++) {
                float v = vs[m * VS_ST + co + lane];
#pragma unroll
                for (int u = 0; u < 4; u++)
                    accv[u] = fmaf(__shfl_sync(0xffffffffu, p1[u], m - 32), v, accv[u]);
            }
#pragma unroll
            for (int u = 0; u < 4; u++) {
                int li = li0 + u;
                if (li < le) {
                    int i2 = li / 7, j2 = li - i2 * 7;
                    size_t oidx = (wrow0 + i2 * 56 + j2) * DIMC + co + lane;
                    float v = accv[u];
                    __nv_bfloat16 h = __float2bfloat16(v);
                    g_attnHi[oidx] = __bfloat16_as_ushort(h);
                    g_attnLo[oidx] = __bfloat16_as_ushort(
                        __float2bfloat16(v - __bfloat162float(h)));
                }
            }
        }
    }
}

// ---------------- launch ---------------------------------------------------
extern "C" void kernel_launch(void* const* d_in, const int* in_sizes, int n_in,
                              void* d_out, int out_size) {
    const float* x  = (const float*)d_in[0];
    const float* Wq = (const float*)d_in[1];
    const float* bq = (const float*)d_in[2];
    const float* Wk = (const float*)d_in[3];
    const float* bk = (const float*)d_in[4];
    const float* Wv = (const float*)d_in[5];
    const float* bv = (const float*)d_in[6];
    const float* Wo = (const float*)d_in[7];
    const float* bo = (const float*)d_in[8];
    float* out = (float*)d_out;

    cudaFuncSetAttribute(gemm_kernel, cudaFuncAttributeMaxDynamicSharedMemorySize,
                         GEMM_SMEM);
    cudaFuncSetAttribute(attn_kernel, cudaFuncAttributeMaxDynamicSharedMemorySize,
                         ATTN_SMEM);

    prep_kernel<<<(NQKV * DIMC + DIMC * DIMC + 255) / 256, 256>>>(Wq, Wk, Wv, Wo,
                                                                  bq, bk, bv);
    xsplit_kernel<<<(int)(((size_t)TOKENS * DIMC / 4) / 256), 256>>>(x);
    gemm_kernel<<<dim3(3, TOKENS / MT), 256, GEMM_SMEM>>>(bo, out, 0);
    attn_kernel<<<4096, 256, ATTN_SMEM>>>();
    gemm_kernel<<<dim3(1, TOKENS / MT), 256, GEMM_SMEM>>>(bo, out, 1);
}

// round 5
// speedup vs baseline: 2.4919x; 1.0275x over previous
#include <cuda_runtime.h>
#include <cuda_bf16.h>
#include <cstdint>

// WindowAttention B=64 56x56 C=192 NH=6 HD=32 WS=7 -> 4096 windows x 49 tokens.
// K0 prep:    W -> W^T bf16 hi/lo, bias concat
// K0b xsplit: x fp32 -> bf16 hi/lo
// K1 gemm0:   qkv = x @ [Wq|Wk|Wv] + b  (mma.sync bf16 3-pass, cp.async pipe)
// K2 attn:    per-window softmax attention; smem-staged packed P, f32x2 AV
// K3 gemm1:   out = attn @ Wo + bo

#define TOKENS 200704
#define DIMC 192
#define NQKV 576
#define LTOK 49
#define SCALE 0.17677669529663687f
#define MT 64
#define NTILE 192
#define KC 48
#define AST 56   // A smem row stride (bf16 elems)
#define BST 48   // B smem row stride

typedef unsigned long long u64;

// ---------------- device scratch ----------------------------------------
__device__ __align__(16) float g_qkv[(size_t)TOKENS * NQKV];
__device__ __align__(16) uint16_t g_xHi[(size_t)TOKENS * DIMC];
__device__ __align__(16) uint16_t g_xLo[(size_t)TOKENS * DIMC];
__device__ __align__(16) uint16_t g_attnHi[(size_t)TOKENS * DIMC];
__device__ __align__(16) uint16_t g_attnLo[(size_t)TOKENS * DIMC];
__device__ __align__(16) uint16_t g_WThi[NQKV * DIMC];
__device__ __align__(16) uint16_t g_WTlo[NQKV * DIMC];
__device__ __align__(16) uint16_t g_WoThi[DIMC * DIMC];
__device__ __align__(16) uint16_t g_WoTlo[DIMC * DIMC];
__device__ __align__(16) float g_bqkv[NQKV];

// ---------------- helpers ------------------------------------------------
__device__ __forceinline__ uint32_t smem_u32(const void* p) {
    uint32_t a;
    asm("{ .reg .u64 t; cvta.to.shared.u64 t, %1; cvt.u32.u64 %0, t; }"
        : "=r"(a) : "l"(p));
    return a;
}
__device__ __forceinline__ u64 pk2(float x) {
    u64 r; asm("mov.b64 %0, {%1, %1};" : "=l"(r) : "f"(x)); return r;
}
__device__ __forceinline__ u64 pkab(float a, float b) {
    u64 r; asm("mov.b64 %0, {%1, %2};" : "=l"(r) : "f"(a), "f"(b)); return r;
}
__device__ __forceinline__ void unpk(u64 v, float& a, float& b) {
    asm("mov.b64 {%0, %1}, %2;" : "=f"(a), "=f"(b) : "l"(v));
}
__device__ __forceinline__ u64 f2fma(u64 a, u64 b, u64 c) {
    u64 d; asm("fma.rn.f32x2 %0, %1, %2, %3;" : "=l"(d) : "l"(a), "l"(b), "l"(c));
    return d;
}
__device__ __forceinline__ void mma_bf16(float d[4], const uint32_t a[4],
                                         const uint32_t b[2]) {
    asm volatile(
        "mma.sync.aligned.m16n8k16.row.col.f32.bf16.bf16.f32 "
        "{%0,%1,%2,%3}, {%4,%5,%6,%7}, {%8,%9}, {%0,%1,%2,%3};"
        : "+f"(d[0]), "+f"(d[1]), "+f"(d[2]), "+f"(d[3])
        : "r"(a[0]), "r"(a[1]), "r"(a[2]), "r"(a[3]), "r"(b[0]), "r"(b[1]));
}
__device__ __forceinline__ uint32_t bf2pack(float x, float y) {
    __nv_bfloat16 hx = __float2bfloat16(x), hy = __float2bfloat16(y);
    return ((uint32_t)__bfloat16_as_ushort(hy) << 16) | __bfloat16_as_ushort(hx);
}
__device__ __forceinline__ void cpa16(uint32_t dst, const void* src) {
    asm volatile("cp.async.cg.shared.global [%0], [%1], 16;"
                 :: "r"(dst), "l"(src));
}
#define CP_COMMIT() asm volatile("cp.async.commit_group;" ::: "memory")
#define CP_WAIT1() asm volatile("cp.async.wait_group 1;" ::: "memory")
#define CP_WAIT0() asm volatile("cp.async.wait_group 0;" ::: "memory")

// ---------------- K0: weight prep ----------------------------------------
__global__ void prep_kernel(const float* __restrict__ Wq, const float* __restrict__ Wk,
                            const float* __restrict__ Wv, const float* __restrict__ Wo,
                            const float* __restrict__ bq, const float* __restrict__ bk,
                            const float* __restrict__ bv) {
    int idx = blockIdx.x * 256 + threadIdx.x;
    if (idx < NQKV * DIMC) {
        int n = idx / DIMC, k = idx - n * DIMC;
        const float* W = (n < 192) ? Wq : (n < 384) ? Wk : Wv;
        float v = W[k * DIMC + (n % 192)];
        __nv_bfloat16 h = __float2bfloat16(v);
        g_WThi[idx] = __bfloat16_as_ushort(h);
        g_WTlo[idx] = __bfloat16_as_ushort(__float2bfloat16(v - __bfloat162float(h)));
        if (idx < NQKV)
            g_bqkv[idx] = (idx < 192) ? bq[idx]
                        : (idx < 384) ? bk[idx - 192] : bv[idx - 384];
    } else if (idx < NQKV * DIMC + DIMC * DIMC) {
        int j = idx - NQKV * DIMC;
        int n = j / DIMC, k = j - n * DIMC;
        float v = Wo[k * DIMC + n];
        __nv_bfloat16 h = __float2bfloat16(v);
        g_WoThi[j] = __bfloat16_as_ushort(h);
        g_WoTlo[j] = __bfloat16_as_ushort(__float2bfloat16(v - __bfloat162float(h)));
    }
}

// ---------------- K0b: x -> bf16 hi/lo -----------------------------------
__global__ void xsplit_kernel(const float* __restrict__ x) {
    size_t i4 = ((size_t)blockIdx.x * 256 + threadIdx.x) * 4;
    float4 v = *(const float4*)(x + i4);
    float hx = __bfloat162float(__float2bfloat16(v.x));
    float hy = __bfloat162float(__float2bfloat16(v.y));
    float hz = __bfloat162float(__float2bfloat16(v.z));
    float hw = __bfloat162float(__float2bfloat16(v.w));
    *(uint2*)(g_xHi + i4) = make_uint2(bf2pack(v.x, v.y), bf2pack(v.z, v.w));
    *(uint2*)(g_xLo + i4) = make_uint2(bf2pack(v.x - hx, v.y - hy),
                                       bf2pack(v.z - hz, v.w - hw));
}

// ---------------- K1/K3: pipelined HMMA GEMM ------------------------------
#define SA_HI 0
#define SA_LO 7168
#define SB_HI 14336
#define SB_LO 32768
#define GEMM_SMEM (51200 * 2)

__device__ __forceinline__ void load_chunk(
    uint32_t sbase, int buf, int c, int tid, size_t arow0, int ncol0,
    const uint16_t* __restrict__ Ahg, const uint16_t* __restrict__ Alg,
    const uint16_t* __restrict__ Bhg, const uint16_t* __restrict__ Blg) {
    for (int idx = tid; idx < MT * 6; idx += 256) {
        int r = idx / 6, kk = idx - r * 6;
        uint32_t off = (uint32_t)(r * AST + kk * 8) * 2;
        size_t gs = (arow0 + r) * DIMC + c * KC + kk * 8;
        cpa16(sbase + (SA_HI + buf * 3584) * 2 + off, Ahg + gs);
        cpa16(sbase + (SA_LO + buf * 3584) * 2 + off, Alg + gs);
    }
    for (int idx = tid; idx < NTILE * 6; idx += 256) {
        int r = idx / 6, kk = idx - r * 6;
        uint32_t off = (uint32_t)(r * BST + kk * 8) * 2;
        size_t gs = (size_t)(ncol0 + r) * DIMC + c * KC + kk * 8;
        cpa16(sbase + (SB_HI + buf * 9216) * 2 + off, Bhg + gs);
        cpa16(sbase + (SB_LO + buf * 9216) * 2 + off, Blg + gs);
    }
}

extern "C" __global__ void __launch_bounds__(256, 2)
gemm_kernel(const float* __restrict__ bo, float* __restrict__ outx, int mode) {
    extern __shared__ uint16_t sm[];
    uint32_t sbase = smem_u32(sm);
    const int tid = threadIdx.x, wid = tid >> 5, lane = tid & 31;
    const int g = lane >> 2, tg = lane & 3;
    const int wm = (wid >> 2) * 32;
    const int wn = (wid & 3) * 48;
    const int mtile = blockIdx.y;
    const int ncol0 = blockIdx.x * NTILE;
    const size_t arow0 = (size_t)mtile * MT;

    const uint16_t* Ahg = mode ? g_attnHi : g_xHi;
    const uint16_t* Alg = mode ? g_attnLo : g_xLo;
    const uint16_t* Bhg = mode ? g_WoThi : g_WThi;
    const uint16_t* Blg = mode ? g_WoTlo : g_WTlo;
    const float* bias = mode ? bo : g_bqkv;
    const int Ntot = mode ? DIMC : NQKV;
    float* outp = mode ? outx : g_qkv;

    float acc[2][6][4];
#pragma unroll
    for (int mi = 0; mi < 2; mi++)
#pragma unroll
        for (int ni = 0; ni < 6; ni++)
#pragma unroll
            for (int q = 0; q < 4; q++) acc[mi][ni][q] = 0.f;

    load_chunk(sbase, 0, 0, tid, arow0, ncol0, Ahg, Alg, Bhg, Blg);
    CP_COMMIT();
    load_chunk(sbase, 1, 1, tid, arow0, ncol0, Ahg, Alg, Bhg, Blg);
    CP_COMMIT();

#pragma unroll
    for (int c = 0; c < 4; c++) {
        if (c < 3) { CP_WAIT1(); } else { CP_WAIT0(); }
        __syncthreads();
        const int buf = c & 1;
        const uint16_t* Ah = sm + SA_HI + buf * 3584;
        const uint16_t* Al = sm + SA_LO + buf * 3584;
        const uint16_t* Bh = sm + SB_HI + buf * 9216;
        const uint16_t* Bl = sm + SB_LO + buf * 9216;
#pragma unroll
        for (int ks = 0; ks < 3; ks++) {
            const int kb = ks * 16;
            uint32_t ah[2][4], al[2][4];
#pragma unroll
            for (int mi = 0; mi < 2; mi++) {
                const uint16_t* ap = Ah + (wm + mi * 16 + g) * AST + kb + tg * 2;
                ah[mi][0] = *(const uint32_t*)(ap);
                ah[mi][1] = *(const uint32_t*)(ap + 8 * AST);
                ah[mi][2] = *(const uint32_t*)(ap + 8);
                ah[mi][3] = *(const uint32_t*)(ap + 8 * AST + 8);
                const uint16_t* alp = Al + (wm + mi * 16 + g) * AST + kb + tg * 2;
                al[mi][0] = *(const uint32_t*)(alp);
                al[mi][1] = *(const uint32_t*)(alp + 8 * AST);
                al[mi][2] = *(const uint32_t*)(alp + 8);
                al[mi][3] = *(const uint32_t*)(alp + 8 * AST + 8);
            }
#pragma unroll
            for (int ni = 0; ni < 6; ni++) {
                const uint16_t* bph = Bh + (wn + ni * 8 + g) * BST + kb + tg * 2;
                const uint16_t* bpl = Bl + (wn + ni * 8 + g) * BST + kb + tg * 2;
                uint32_t bh[2] = {*(const uint32_t*)bph, *(const uint32_t*)(bph + 8)};
                uint32_t bl[2] = {*(const uint32_t*)bpl, *(const uint32_t*)(bpl + 8)};
                mma_bf16(acc[0][ni], ah[0], bh);
                mma_bf16(acc[1][ni], ah[1], bh);
                mma_bf16(acc[0][ni], ah[0], bl);
                mma_bf16(acc[1][ni], ah[1], bl);
                mma_bf16(acc[0][ni], al[0], bh);
                mma_bf16(acc[1][ni], al[1], bh);
            }
        }
        if (c + 2 < 4) {
            __syncthreads();
            load_chunk(sbase, buf, c + 2, tid, arow0, ncol0, Ahg, Alg, Bhg, Blg);
            CP_COMMIT();
        }
    }

#pragma unroll
    for (int mi = 0; mi < 2; mi++) {
        size_t r0 = arow0 + wm + mi * 16 + g;
#pragma unroll
        for (int ni = 0; ni < 6; ni++) {
            int cg = ncol0 + wn + ni * 8 + tg * 2;
            float2 bb = *(const float2*)(bias + cg);
            float2 o0 = {acc[mi][ni][0] + bb.x, acc[mi][ni][1] + bb.y};
            float2 o1 = {acc[mi][ni][2] + bb.x, acc[mi][ni][3] + bb.y};
            *(float2*)(outp + r0 * Ntot + cg) = o0;
            *(float2*)(outp + (r0 + 8) * Ntot + cg) = o1;
        }
    }
}

// ---------------- K2: per-window attention --------------------------------
// smem: qs[49*192] + vs[49*192] floats + prow[8 warps][4 pairs][64 m] u64
#define ATTN_SMEM (LTOK * 384 * 4 + 8 * 4 * 64 * 8)   // 75264 + 16384 = 91648

extern "C" __global__ void __launch_bounds__(256, 2) attn_kernel() {
    extern __shared__ float sf[];
    float* qs = sf;
    float* vs = qs + LTOK * 192;
    u64* prow = (u64*)(sf + LTOK * 384);

    const int tid = threadIdx.x;
    const int warp = tid >> 5, lane = tid & 31;
    const int widx = blockIdx.x;
    const int b = widx >> 6, wh = (widx >> 3) & 7, ww = widx & 7;
    const size_t wrow0 = (size_t)b * 3136 + (size_t)wh * 7 * 56 + ww * 7;

    // stage Q and V into smem (K read direct from gmem later)
    for (int idx = tid; idx < LTOK * 48; idx += 256) {
        int l = idx / 48, kq = idx - l * 48;
        int i = l / 7, j = l - i * 7;
        const float* src = g_qkv + (wrow0 + i * 56 + j) * NQKV + kq * 4;
        *(float4*)&qs[l * 192 + kq * 4] = *(const float4*)(src);
        *(float4*)&vs[l * 192 + kq * 4] = *(const float4*)(src + 384);
    }
    __syncthreads();

    const int m1 = lane, m2 = lane + 32;
    const bool v2 = (m2 < LTOK);
    const int m2c = v2 ? m2 : (LTOK - 1);
    const size_t r1 = wrow0 + (m1 / 7) * 56 + (m1 % 7);
    const size_t r2 = wrow0 + (m2c / 7) * 56 + (m2c % 7);
    const int qstart[4] = {0, 13, 26, 39};
    const int qend[4] = {13, 26, 39, 49};
    u64* pw = prow + warp * 256;

    for (int t = warp; t < 24; t += 8) {
        const int h = t >> 2, par = t & 3, co = h * 32;

        // K rows direct from gmem -> registers, interleaved (m, m+32) pairs
        u64 kp[32];
        {
            const float4* k1p = (const float4*)(g_qkv + r1 * NQKV + 192 + co);
            const float4* k2p = (const float4*)(g_qkv + r2 * NQKV + 192 + co);
#pragma unroll
            for (int d4 = 0; d4 < 8; d4++) {
                float4 ka = k1p[d4];
                float4 kb = k2p[d4];
                kp[d4 * 4 + 0] = pkab(ka.x, kb.x);
                kp[d4 * 4 + 1] = pkab(ka.y, kb.y);
                kp[d4 * 4 + 2] = pkab(ka.z, kb.z);
                kp[d4 * 4 + 3] = pkab(ka.w, kb.w);
            }
        }

        const int ls = qstart[par], le = qend[par];
        for (int li0 = ls; li0 < le; li0 += 8) {
            float p0[8], p1[8];
#pragma unroll
            for (int u = 0; u < 8; u++) {
                int li = li0 + u;
                int lic = (li < le) ? li : ls;
                u64 s01 = 0ull;
#pragma unroll
                for (int d4 = 0; d4 < 8; d4++) {
                    float4 qv = *(const float4*)&qs[lic * 192 + co + d4 * 4];
                    s01 = f2fma(pk2(qv.x), kp[d4 * 4 + 0], s01);
                    s01 = f2fma(pk2(qv.y), kp[d4 * 4 + 1], s01);
                    s01 = f2fma(pk2(qv.z), kp[d4 * 4 + 2], s01);
                    s01 = f2fma(pk2(qv.w), kp[d4 * 4 + 3], s01);
                }
                float s0, s1;
                unpk(s01, s0, s1);
                float e0 = __expf(s0 * SCALE);
                float e1 = v2 ? __expf(s1 * SCALE) : 0.f;
                float sum = e0 + e1;
#pragma unroll
                for (int o = 16; o > 0; o >>= 1)
                    sum += __shfl_xor_sync(0xffffffffu, sum, o);
                float inv = __fdividef(1.f, sum);
                p0[u] = e0 * inv;
                p1[u] = e1 * inv;
            }

            // stage packed P pairs: prow[pair][m] = (p[2j][m], p[2j+1][m])
#pragma unroll
            for (int j = 0; j < 4; j++) {
                pw[j * 64 + m1] = pkab(p0[2 * j], p0[2 * j + 1]);
                pw[j * 64 + m2] = pkab(p1[2 * j], p1[2 * j + 1]);
            }
            __syncwarp();

            // AV: lane owns d = lane; accumulate 4 u-pairs with f32x2
            u64 acc[4] = {0ull, 0ull, 0ull, 0ull};
#pragma unroll 6
            for (int mh = 0; mh < 24; mh++) {
                const int m0 = mh * 2;
                float va = vs[m0 * 192 + co + lane];
                float vb = vs[(m0 + 1) * 192 + co + lane];
                u64 wa = pk2(va), wb = pk2(vb);
#pragma unroll
                for (int j = 0; j < 4; j++) {
                    ulonglong2 pp = *(const ulonglong2*)&pw[j * 64 + m0];
                    acc[j] = f2fma(pp.x, wa, acc[j]);
                    acc[j] = f2fma(pp.y, wb, acc[j]);
                }
            }
            {
                u64 wc = pk2(vs[48 * 192 + co + lane]);
#pragma unroll
                for (int j = 0; j < 4; j++)
                    acc[j] = f2fma(pw[j * 64 + 48], wc, acc[j]);
            }
            __syncwarp();

            float accv[8];
#pragma unroll
            for (int j = 0; j < 4; j++) unpk(acc[j], accv[2 * j], accv[2 * j + 1]);
#pragma unroll
            for (int u = 0; u < 8; u++) {
                int li = li0 + u;
                if (li < le) {
                    int i2 = li / 7, j2 = li - i2 * 7;
                    size_t oidx = (wrow0 + i2 * 56 + j2) * DIMC + co + lane;
                    float v = accv[u];
                    __nv_bfloat16 hh = __float2bfloat16(v);
                    g_attnHi[oidx] = __bfloat16_as_ushort(hh);
                    g_attnLo[oidx] = __bfloat16_as_ushort(
                        __float2bfloat16(v - __bfloat162float(hh)));
                }
            }
        }
    }
}

// ---------------- launch ---------------------------------------------------
extern "C" void kernel_launch(void* const* d_in, const int* in_sizes, int n_in,
                              void* d_out, int out_size) {
    const float* x  = (const float*)d_in[0];
    const float* Wq = (const float*)d_in[1];
    const float* bq = (const float*)d_in[2];
    const float* Wk = (const float*)d_in[3];
    const float* bk = (const float*)d_in[4];
    const float* Wv = (const float*)d_in[5];
    const float* bv = (const float*)d_in[6];
    const float* Wo = (const float*)d_in[7];
    const float* bo = (const float*)d_in[8];
    float* out = (float*)d_out;

    cudaFuncSetAttribute(gemm_kernel, cudaFuncAttributeMaxDynamicSharedMemorySize,
                         GEMM_SMEM);
    cudaFuncSetAttribute(attn_kernel, cudaFuncAttributeMaxDynamicSharedMemorySize,
                         ATTN_SMEM);

    prep_kernel<<<(NQKV * DIMC + DIMC * DIMC + 255) / 256, 256>>>(Wq, Wk, Wv, Wo,
                                                                  bq, bk, bv);
    xsplit_kernel<<<(int)(((size_t)TOKENS * DIMC / 4) / 256), 256>>>(x);
    gemm_kernel<<<dim3(3, TOKENS / MT), 256, GEMM_SMEM>>>(bo, out, 0);
    attn_kernel<<<4096, 256, ATTN_SMEM>>>();
    gemm_kernel<<<dim3(1, TOKENS / MT), 256, GEMM_SMEM>>>(bo, out, 1);
}

// round 6
// speedup vs baseline: 2.4922x; 1.0001x over previous
#include <cuda_runtime.h>
#include <cuda_bf16.h>
#include <cstdint>

// WindowAttention B=64 56x56 C=192 NH=6 HD=32 WS=7 -> 4096 windows x 49 tokens.
// K0 prep:    W -> W^T bf16 hi/lo, bias concat
// K0b xsplit: x fp32 -> bf16 hi/lo
// K1 gemm0:   qkv = x @ [Wq|Wk|Wv] + b  (mma.sync bf16 3-pass, cp.async pipe)
// K2 attn:    per-window softmax attention; smem-staged packed P, f32x2 AV
// K3 gemm1:   out = attn @ Wo + bo

#define TOKENS 200704
#define DIMC 192
#define NQKV 576
#define LTOK 49
#define SCALE 0.17677669529663687f
#define MT 64
#define NTILE 192
#define KC 48
#define AST 56   // A smem row stride (bf16 elems)
#define BST 48   // B smem row stride

typedef unsigned long long u64;

// ---------------- device scratch ----------------------------------------
__device__ __align__(16) float g_qkv[(size_t)TOKENS * NQKV];
__device__ __align__(16) uint16_t g_xHi[(size_t)TOKENS * DIMC];
__device__ __align__(16) uint16_t g_xLo[(size_t)TOKENS * DIMC];
__device__ __align__(16) uint16_t g_attnHi[(size_t)TOKENS * DIMC];
__device__ __align__(16) uint16_t g_attnLo[(size_t)TOKENS * DIMC];
__device__ __align__(16) uint16_t g_WThi[NQKV * DIMC];
__device__ __align__(16) uint16_t g_WTlo[NQKV * DIMC];
__device__ __align__(16) uint16_t g_WoThi[DIMC * DIMC];
__device__ __align__(16) uint16_t g_WoTlo[DIMC * DIMC];
__device__ __align__(16) float g_bqkv[NQKV];

// ---------------- helpers ------------------------------------------------
__device__ __forceinline__ uint32_t smem_u32(const void* p) {
    uint32_t a;
    asm("{ .reg .u64 t; cvta.to.shared.u64 t, %1; cvt.u32.u64 %0, t; }"
        : "=r"(a) : "l"(p));
    return a;
}
__device__ __forceinline__ u64 pk2(float x) {
    u64 r; asm("mov.b64 %0, {%1, %1};" : "=l"(r) : "f"(x)); return r;
}
__device__ __forceinline__ u64 pkab(float a, float b) {
    u64 r; asm("mov.b64 %0, {%1, %2};" : "=l"(r) : "f"(a), "f"(b)); return r;
}
__device__ __forceinline__ void unpk(u64 v, float& a, float& b) {
    asm("mov.b64 {%0, %1}, %2;" : "=f"(a), "=f"(b) : "l"(v));
}
__device__ __forceinline__ u64 f2fma(u64 a, u64 b, u64 c) {
    u64 d; asm("fma.rn.f32x2 %0, %1, %2, %3;" : "=l"(d) : "l"(a), "l"(b), "l"(c));
    return d;
}
__device__ __forceinline__ void mma_bf16(float d[4], const uint32_t a[4],
                                         const uint32_t b[2]) {
    asm volatile(
        "mma.sync.aligned.m16n8k16.row.col.f32.bf16.bf16.f32 "
        "{%0,%1,%2,%3}, {%4,%5,%6,%7}, {%8,%9}, {%0,%1,%2,%3};"
        : "+f"(d[0]), "+f"(d[1]), "+f"(d[2]), "+f"(d[3])
        : "r"(a[0]), "r"(a[1]), "r"(a[2]), "r"(a[3]), "r"(b[0]), "r"(b[1]));
}
__device__ __forceinline__ uint32_t bf2pack(float x, float y) {
    __nv_bfloat16 hx = __float2bfloat16(x), hy = __float2bfloat16(y);
    return ((uint32_t)__bfloat16_as_ushort(hy) << 16) | __bfloat16_as_ushort(hx);
}
__device__ __forceinline__ void cpa16(uint32_t dst, const void* src) {
    asm volatile("cp.async.cg.shared.global [%0], [%1], 16;"
                 :: "r"(dst), "l"(src));
}
#define CP_COMMIT() asm volatile("cp.async.commit_group;" ::: "memory")
#define CP_WAIT1() asm volatile("cp.async.wait_group 1;" ::: "memory")
#define CP_WAIT0() asm volatile("cp.async.wait_group 0;" ::: "memory")

// ---------------- K0: weight prep ----------------------------------------
__global__ void prep_kernel(const float* __restrict__ Wq, const float* __restrict__ Wk,
                            const float* __restrict__ Wv, const float* __restrict__ Wo,
                            const float* __restrict__ bq, const float* __restrict__ bk,
                            const float* __restrict__ bv) {
    int idx = blockIdx.x * 256 + threadIdx.x;
    if (idx < NQKV * DIMC) {
        int n = idx / DIMC, k = idx - n * DIMC;
        const float* W = (n < 192) ? Wq : (n < 384) ? Wk : Wv;
        float v = W[k * DIMC + (n % 192)];
        __nv_bfloat16 h = __float2bfloat16(v);
        g_WThi[idx] = __bfloat16_as_ushort(h);
        g_WTlo[idx] = __bfloat16_as_ushort(__float2bfloat16(v - __bfloat162float(h)));
        if (idx < NQKV)
            g_bqkv[idx] = (idx < 192) ? bq[idx]
                        : (idx < 384) ? bk[idx - 192] : bv[idx - 384];
    } else if (idx < NQKV * DIMC + DIMC * DIMC) {
        int j = idx - NQKV * DIMC;
        int n = j / DIMC, k = j - n * DIMC;
        float v = Wo[k * DIMC + n];
        __nv_bfloat16 h = __float2bfloat16(v);
        g_WoThi[j] = __bfloat16_as_ushort(h);
        g_WoTlo[j] = __bfloat16_as_ushort(__float2bfloat16(v - __bfloat162float(h)));
    }
}

// ---------------- K0b: x -> bf16 hi/lo -----------------------------------
__global__ void xsplit_kernel(const float* __restrict__ x) {
    size_t i4 = ((size_t)blockIdx.x * 256 + threadIdx.x) * 4;
    float4 v = *(const float4*)(x + i4);
    float hx = __bfloat162float(__float2bfloat16(v.x));
    float hy = __bfloat162float(__float2bfloat16(v.y));
    float hz = __bfloat162float(__float2bfloat16(v.z));
    float hw = __bfloat162float(__float2bfloat16(v.w));
    *(uint2*)(g_xHi + i4) = make_uint2(bf2pack(v.x, v.y), bf2pack(v.z, v.w));
    *(uint2*)(g_xLo + i4) = make_uint2(bf2pack(v.x - hx, v.y - hy),
                                       bf2pack(v.z - hz, v.w - hw));
}

// ---------------- K1/K3: pipelined HMMA GEMM ------------------------------
#define SA_HI 0
#define SA_LO 7168
#define SB_HI 14336
#define SB_LO 32768
#define GEMM_SMEM (51200 * 2)

__device__ __forceinline__ void load_chunk(
    uint32_t sbase, int buf, int c, int tid, size_t arow0, int ncol0,
    const uint16_t* __restrict__ Ahg, const uint16_t* __restrict__ Alg,
    const uint16_t* __restrict__ Bhg, const uint16_t* __restrict__ Blg) {
    for (int idx = tid; idx < MT * 6; idx += 256) {
        int r = idx / 6, kk = idx - r * 6;
        uint32_t off = (uint32_t)(r * AST + kk * 8) * 2;
        size_t gs = (arow0 + r) * DIMC + c * KC + kk * 8;
        cpa16(sbase + (SA_HI + buf * 3584) * 2 + off, Ahg + gs);
        cpa16(sbase + (SA_LO + buf * 3584) * 2 + off, Alg + gs);
    }
    for (int idx = tid; idx < NTILE * 6; idx += 256) {
        int r = idx / 6, kk = idx - r * 6;
        uint32_t off = (uint32_t)(r * BST + kk * 8) * 2;
        size_t gs = (size_t)(ncol0 + r) * DIMC + c * KC + kk * 8;
        cpa16(sbase + (SB_HI + buf * 9216) * 2 + off, Bhg + gs);
        cpa16(sbase + (SB_LO + buf * 9216) * 2 + off, Blg + gs);
    }
}

extern "C" __global__ void __launch_bounds__(256, 2)
gemm_kernel(const float* __restrict__ bo, float* __restrict__ outx, int mode) {
    extern __shared__ uint16_t sm[];
    uint32_t sbase = smem_u32(sm);
    const int tid = threadIdx.x, wid = tid >> 5, lane = tid & 31;
    const int g = lane >> 2, tg = lane & 3;
    const int wm = (wid >> 2) * 32;
    const int wn = (wid & 3) * 48;
    const int mtile = blockIdx.y;
    const int ncol0 = blockIdx.x * NTILE;
    const size_t arow0 = (size_t)mtile * MT;

    const uint16_t* Ahg = mode ? g_attnHi : g_xHi;
    const uint16_t* Alg = mode ? g_attnLo : g_xLo;
    const uint16_t* Bhg = mode ? g_WoThi : g_WThi;
    const uint16_t* Blg = mode ? g_WoTlo : g_WTlo;
    const float* bias = mode ? bo : g_bqkv;
    const int Ntot = mode ? DIMC : NQKV;
    float* outp = mode ? outx : g_qkv;

    float acc[2][6][4];
#pragma unroll
    for (int mi = 0; mi < 2; mi++)
#pragma unroll
        for (int ni = 0; ni < 6; ni++)
#pragma unroll
            for (int q = 0; q < 4; q++) acc[mi][ni][q] = 0.f;

    load_chunk(sbase, 0, 0, tid, arow0, ncol0, Ahg, Alg, Bhg, Blg);
    CP_COMMIT();
    load_chunk(sbase, 1, 1, tid, arow0, ncol0, Ahg, Alg, Bhg, Blg);
    CP_COMMIT();

#pragma unroll
    for (int c = 0; c < 4; c++) {
        if (c < 3) { CP_WAIT1(); } else { CP_WAIT0(); }
        __syncthreads();
        const int buf = c & 1;
        const uint16_t* Ah = sm + SA_HI + buf * 3584;
        const uint16_t* Al = sm + SA_LO + buf * 3584;
        const uint16_t* Bh = sm + SB_HI + buf * 9216;
        const uint16_t* Bl = sm + SB_LO + buf * 9216;
#pragma unroll
        for (int ks = 0; ks < 3; ks++) {
            const int kb = ks * 16;
            uint32_t ah[2][4], al[2][4];
#pragma unroll
            for (int mi = 0; mi < 2; mi++) {
                const uint16_t* ap = Ah + (wm + mi * 16 + g) * AST + kb + tg * 2;
                ah[mi][0] = *(const uint32_t*)(ap);
                ah[mi][1] = *(const uint32_t*)(ap + 8 * AST);
                ah[mi][2] = *(const uint32_t*)(ap + 8);
                ah[mi][3] = *(const uint32_t*)(ap + 8 * AST + 8);
                const uint16_t* alp = Al + (wm + mi * 16 + g) * AST + kb + tg * 2;
                al[mi][0] = *(const uint32_t*)(alp);
                al[mi][1] = *(const uint32_t*)(alp + 8 * AST);
                al[mi][2] = *(const uint32_t*)(alp + 8);
                al[mi][3] = *(const uint32_t*)(alp + 8 * AST + 8);
            }
#pragma unroll
            for (int ni = 0; ni < 6; ni++) {
                const uint16_t* bph = Bh + (wn + ni * 8 + g) * BST + kb + tg * 2;
                const uint16_t* bpl = Bl + (wn + ni * 8 + g) * BST + kb + tg * 2;
                uint32_t bh[2] = {*(const uint32_t*)bph, *(const uint32_t*)(bph + 8)};
                uint32_t bl[2] = {*(const uint32_t*)bpl, *(const uint32_t*)(bpl + 8)};
                mma_bf16(acc[0][ni], ah[0], bh);
                mma_bf16(acc[1][ni], ah[1], bh);
                mma_bf16(acc[0][ni], ah[0], bl);
                mma_bf16(acc[1][ni], ah[1], bl);
                mma_bf16(acc[0][ni], al[0], bh);
                mma_bf16(acc[1][ni], al[1], bh);
            }
        }
        if (c + 2 < 4) {
            __syncthreads();
            load_chunk(sbase, buf, c + 2, tid, arow0, ncol0, Ahg, Alg, Bhg, Blg);
            CP_COMMIT();
        }
    }

#pragma unroll
    for (int mi = 0; mi < 2; mi++) {
        size_t r0 = arow0 + wm + mi * 16 + g;
#pragma unroll
        for (int ni = 0; ni < 6; ni++) {
            int cg = ncol0 + wn + ni * 8 + tg * 2;
            float2 bb = *(const float2*)(bias + cg);
            float2 o0 = {acc[mi][ni][0] + bb.x, acc[mi][ni][1] + bb.y};
            float2 o1 = {acc[mi][ni][2] + bb.x, acc[mi][ni][3] + bb.y};
            *(float2*)(outp + r0 * Ntot + cg) = o0;
            *(float2*)(outp + (r0 + 8) * Ntot + cg) = o1;
        }
    }
}

// ---------------- K2: per-window attention --------------------------------
// smem: qs[49*192] + vs[49*192] floats + prow[8 warps][4 pairs][64 m] u64
#define ATTN_SMEM (LTOK * 384 * 4 + 8 * 4 * 64 * 8)   // 75264 + 16384 = 91648

extern "C" __global__ void __launch_bounds__(256, 2) attn_kernel() {
    extern __shared__ float sf[];
    float* qs = sf;
    float* vs = qs + LTOK * 192;
    u64* prow = (u64*)(sf + LTOK * 384);

    const int tid = threadIdx.x;
    const int warp = tid >> 5, lane = tid & 31;
    const int widx = blockIdx.x;
    const int b = widx >> 6, wh = (widx >> 3) & 7, ww = widx & 7;
    const size_t wrow0 = (size_t)b * 3136 + (size_t)wh * 7 * 56 + ww * 7;

    // stage Q and V into smem (K read direct from gmem later)
    for (int idx = tid; idx < LTOK * 48; idx += 256) {
        int l = idx / 48, kq = idx - l * 48;
        int i = l / 7, j = l - i * 7;
        const float* src = g_qkv + (wrow0 + i * 56 + j) * NQKV + kq * 4;
        *(float4*)&qs[l * 192 + kq * 4] = *(const float4*)(src);
        *(float4*)&vs[l * 192 + kq * 4] = *(const float4*)(src + 384);
    }
    __syncthreads();

    const int m1 = lane, m2 = lane + 32;
    const bool v2 = (m2 < LTOK);
    const int m2c = v2 ? m2 : (LTOK - 1);
    const size_t r1 = wrow0 + (m1 / 7) * 56 + (m1 % 7);
    const size_t r2 = wrow0 + (m2c / 7) * 56 + (m2c % 7);
    const int qstart[4] = {0, 13, 26, 39};
    const int qend[4] = {13, 26, 39, 49};
    u64* pw = prow + warp * 256;

    for (int t = warp; t < 24; t += 8) {
        const int h = t >> 2, par = t & 3, co = h * 32;

        // K rows direct from gmem -> registers, interleaved (m, m+32) pairs
        u64 kp[32];
        {
            const float4* k1p = (const float4*)(g_qkv + r1 * NQKV + 192 + co);
            const float4* k2p = (const float4*)(g_qkv + r2 * NQKV + 192 + co);
#pragma unroll
            for (int d4 = 0; d4 < 8; d4++) {
                float4 ka = k1p[d4];
                float4 kb = k2p[d4];
                kp[d4 * 4 + 0] = pkab(ka.x, kb.x);
                kp[d4 * 4 + 1] = pkab(ka.y, kb.y);
                kp[d4 * 4 + 2] = pkab(ka.z, kb.z);
                kp[d4 * 4 + 3] = pkab(ka.w, kb.w);
            }
        }

        const int ls = qstart[par], le = qend[par];
        for (int li0 = ls; li0 < le; li0 += 8) {
            float p0[8], p1[8];
#pragma unroll
            for (int u = 0; u < 8; u++) {
                int li = li0 + u;
                int lic = (li < le) ? li : ls;
                u64 s01 = 0ull;
#pragma unroll
                for (int d4 = 0; d4 < 8; d4++) {
                    float4 qv = *(const float4*)&qs[lic * 192 + co + d4 * 4];
                    s01 = f2fma(pk2(qv.x), kp[d4 * 4 + 0], s01);
                    s01 = f2fma(pk2(qv.y), kp[d4 * 4 + 1], s01);
                    s01 = f2fma(pk2(qv.z), kp[d4 * 4 + 2], s01);
                    s01 = f2fma(pk2(qv.w), kp[d4 * 4 + 3], s01);
                }
                float s0, s1;
                unpk(s01, s0, s1);
                float e0 = __expf(s0 * SCALE);
                float e1 = v2 ? __expf(s1 * SCALE) : 0.f;
                float sum = e0 + e1;
#pragma unroll
                for (int o = 16; o > 0; o >>= 1)
                    sum += __shfl_xor_sync(0xffffffffu, sum, o);
                float inv = __fdividef(1.f, sum);
                p0[u] = e0 * inv;
                p1[u] = e1 * inv;
            }

            // stage packed P pairs: prow[pair][m] = (p[2j][m], p[2j+1][m])
#pragma unroll
            for (int j = 0; j < 4; j++) {
                pw[j * 64 + m1] = pkab(p0[2 * j], p0[2 * j + 1]);
                pw[j * 64 + m2] = pkab(p1[2 * j], p1[2 * j + 1]);
            }
            __syncwarp();

            // AV: lane owns d = lane; accumulate 4 u-pairs with f32x2
            u64 acc[4] = {0ull, 0ull, 0ull, 0ull};
#pragma unroll 6
            for (int mh = 0; mh < 24; mh++) {
                const int m0 = mh * 2;
                float va = vs[m0 * 192 + co + lane];
                float vb = vs[(m0 + 1) * 192 + co + lane];
                u64 wa = pk2(va), wb = pk2(vb);
#pragma unroll
                for (int j = 0; j < 4; j++) {
                    ulonglong2 pp = *(const ulonglong2*)&pw[j * 64 + m0];
                    acc[j] = f2fma(pp.x, wa, acc[j]);
                    acc[j] = f2fma(pp.y, wb, acc[j]);
                }
            }
            {
                u64 wc = pk2(vs[48 * 192 + co + lane]);
#pragma unroll
                for (int j = 0; j < 4; j++)
                    acc[j] = f2fma(pw[j * 64 + 48], wc, acc[j]);
            }
            __syncwarp();

            float accv[8];
#pragma unroll
            for (int j = 0; j < 4; j++) unpk(acc[j], accv[2 * j], accv[2 * j + 1]);
#pragma unroll
            for (int u = 0; u < 8; u++) {
                int li = li0 + u;
                if (li < le) {
                    int i2 = li / 7, j2 = li - i2 * 7;
                    size_t oidx = (wrow0 + i2 * 56 + j2) * DIMC + co + lane;
                    float v = accv[u];
                    __nv_bfloat16 hh = __float2bfloat16(v);
                    g_attnHi[oidx] = __bfloat16_as_ushort(hh);
                    g_attnLo[oidx] = __bfloat16_as_ushort(
                        __float2bfloat16(v - __bfloat162float(hh)));
                }
            }
        }
    }
}

// ---------------- launch ---------------------------------------------------
extern "C" void kernel_launch(void* const* d_in, const int* in_sizes, int n_in,
                              void* d_out, int out_size) {
    const float* x  = (const float*)d_in[0];
    const float* Wq = (const float*)d_in[1];
    const float* bq = (const float*)d_in[2];
    const float* Wk = (const float*)d_in[3];
    const float* bk = (const float*)d_in[4];
    const float* Wv = (const float*)d_in[5];
    const float* bv = (const float*)d_in[6];
    const float* Wo = (const float*)d_in[7];
    const float* bo = (const float*)d_in[8];
    float* out = (float*)d_out;

    cudaFuncSetAttribute(gemm_kernel, cudaFuncAttributeMaxDynamicSharedMemorySize,
                         GEMM_SMEM);
    cudaFuncSetAttribute(attn_kernel, cudaFuncAttributeMaxDynamicSharedMemorySize,
                         ATTN_SMEM);

    prep_kernel<<<(NQKV * DIMC + DIMC * DIMC + 255) / 256, 256>>>(Wq, Wk, Wv, Wo,
                                                                  bq, bk, bv);
    xsplit_kernel<<<(int)(((size_t)TOKENS * DIMC / 4) / 256), 256>>>(x);
    gemm_kernel<<<dim3(3, TOKENS / MT), 256, GEMM_SMEM>>>(bo, out, 0);
    attn_kernel<<<4096, 256, ATTN_SMEM>>>();
    gemm_kernel<<<dim3(1, TOKENS / MT), 256, GEMM_SMEM>>>(bo, out, 1);
}